// round 10
// baseline (speedup 1.0000x reference)
#include <cuda_runtime.h>
#include <cuda_bf16.h>

#define T_STEPS 100
#define BATCH   2048
#define NH      128
#define NORD    6
#define NSP     512

typedef unsigned long long ull;
typedef unsigned int u32;

// Scratch (device globals — no allocations allowed). Split bf16 planes.
__device__ __align__(16) __nv_bfloat16 g_Hh[(size_t)T_STEPS * BATCH * NH];
__device__ __align__(16) __nv_bfloat16 g_Hl[(size_t)T_STEPS * BATCH * NH];
__device__ __align__(16) float g_h0[BATCH * NH];
__device__ __align__(16) float g_m0[BATCH * NORD];
__device__ __align__(16) __nv_bfloat16 g_Wch[NSP * NH];
__device__ __align__(16) __nv_bfloat16 g_Wcl[NSP * NH];
__device__ __align__(16) float g_bc[NSP];
__device__ __align__(16) __nv_bfloat16 g_W3h[136 * 144];
__device__ __align__(16) __nv_bfloat16 g_W3l[136 * 144];

__device__ __forceinline__ void ffma2(ull &d, ull a, ull b) {
    asm("fma.rn.f32x2 %0, %1, %2, %0;" : "+l"(d) : "l"(a), "l"(b));
}
__device__ __forceinline__ float sum2(ull a) {
    float lo, hi;
    asm("mov.b64 {%0,%1}, %2;" : "=f"(lo), "=f"(hi) : "l"(a));
    return lo + hi;
}
__device__ __forceinline__ u32 smem_u32(const void* p) {
    u32 a;
    asm("{ .reg .u64 t; cvta.to.shared.u64 t, %1; cvt.u32.u64 %0, t; }" : "=r"(a) : "l"(p));
    return a;
}
__device__ __forceinline__ __nv_bfloat162 split_bf(float x) {
    __nv_bfloat16 hi = __float2bfloat16(x);
    __nv_bfloat16 lo = __float2bfloat16(x - __bfloat162float(hi));
    __nv_bfloat162 r; r.x = hi; r.y = lo; return r;
}
__device__ __forceinline__ u32 us(__nv_bfloat16 b) {
    return (u32)__bfloat16_as_ushort(b);
}
__device__ __forceinline__ void ldsm4(u32* r, u32 addr) {
    asm volatile("ldmatrix.sync.aligned.m8n8.x4.shared.b16 {%0,%1,%2,%3}, [%4];"
        : "=r"(r[0]), "=r"(r[1]), "=r"(r[2]), "=r"(r[3]) : "r"(addr));
}
__device__ __forceinline__ void mma16816(float* c, const u32* a, const u32* b) {
    asm volatile(
        "mma.sync.aligned.m16n8k16.row.col.f32.bf16.bf16.f32 "
        "{%0,%1,%2,%3}, {%4,%5,%6,%7}, {%8,%9}, {%0,%1,%2,%3};"
        : "+f"(c[0]), "+f"(c[1]), "+f"(c[2]), "+f"(c[3])
        : "r"(a[0]), "r"(a[1]), "r"(a[2]), "r"(a[3]), "r"(b[0]), "r"(b[1]));
}
__device__ __forceinline__ void cp16(u32 s, const void* g) {
    asm volatile("cp.async.cg.shared.global [%0], [%1], 16;" :: "r"(s), "l"(g));
}

// ---------------------------------------------------------------------------
// Kernel 1 (merged init): grid 513, dynamic smem 50KB -> 4 CTAs/SM, 1 wave.
// ---------------------------------------------------------------------------
__global__ void __launch_bounds__(128) k_init(
    const float* __restrict__ ssp,   const float* __restrict__ w_c,
    const float* __restrict__ w_h,   const float* __restrict__ W_lin,
    const float* __restrict__ b_lin, const float* __restrict__ W_ssp,
    const float* __restrict__ b_ssp, const float* __restrict__ he,
    const float* __restrict__ me,    const float* __restrict__ ie,
    const float* __restrict__ ik,    const float* __restrict__ hk,
    const float* __restrict__ mk,    const float* __restrict__ AT,
    const float* __restrict__ BT) {
    extern __shared__ float s[];        // setup: ssp 8x512 | w_h tile 128x68
    float* s_ssp = s;
    float* s_wh  = s + 4096;
    const int tid = threadIdx.x;
    const int bid = blockIdx.x;

    if (bid < 256) {
        // ---- setup: h0, m0 for 8 batch rows. w_h staged per 64-K tile ----
        const int b0 = bid * 8;
        for (int i = tid; i < 1024; i += 128)
            ((float4*)s_ssp)[i] = ((const float4*)(ssp + (size_t)b0 * 512))[i];

        ull acc[8];
        #pragma unroll
        for (int r = 0; r < 8; r++) acc[r] = 0ull;

        #pragma unroll 1
        for (int kt = 0; kt < 8; kt++) {
            __syncthreads();   // s_wh reuse + (kt==0) ssp ready
            for (int i = tid; i < 2048; i += 128) {
                const int row = i >> 4, c4 = i & 15;
                const float4 v = *(const float4*)(w_h + row * 512 + kt * 64 + c4 * 4);
                *(float4*)(s_wh + row * 68 + c4 * 4) = v;
            }
            __syncthreads();
            #pragma unroll 4
            for (int c4 = 0; c4 < 16; c4++) {
                const ulonglong2 wp = *(const ulonglong2*)(s_wh + tid * 68 + c4 * 4);
                #pragma unroll
                for (int r = 0; r < 8; r++) {
                    const ulonglong2 xp =
                        *(const ulonglong2*)(s_ssp + r * 512 + kt * 64 + c4 * 4);
                    ffma2(acc[r], xp.x, wp.x);
                    ffma2(acc[r], xp.y, wp.y);
                }
            }
        }
        #pragma unroll
        for (int r = 0; r < 8; r++) g_h0[(size_t)(b0 + r) * NH + tid] = sum2(acc[r]);

        if (tid < 48) {
            const int o = tid >> 3, r = tid & 7;
            const float* wc = w_c + o * 512;
            float a0 = 0.f, a1 = 0.f, a2 = 0.f, a3 = 0.f;
            for (int k = 0; k < 512; k += 4) {
                const float4 w4 = *(const float4*)(wc + k);
                const float4 x4 = *(const float4*)(s_ssp + r * 512 + k);
                a0 += x4.x * w4.x; a1 += x4.y * w4.y;
                a2 += x4.z * w4.z; a3 += x4.w * w4.w;
            }
            g_m0[(size_t)(b0 + r) * NORD + o] = (a0 + a1) + (a2 + a3);
        }
    } else if (bid < 512) {
        // ---- combine: 2 output rows of Wc ----
        const int i0 = (bid - 256) * 2;
        for (int i = tid; i < 2 * 512; i += 128) s[i] = W_ssp[(size_t)i0 * 512 + i];
        __syncthreads();
        float acc0 = 0.f, acc1 = 0.f;
        for (int j = 0; j < 512; j++) {
            const float wl = W_lin[j * 128 + tid];
            acc0 += s[j] * wl;
            acc1 += s[512 + j] * wl;
        }
        {
            const __nv_bfloat162 p0 = split_bf(acc0), p1 = split_bf(acc1);
            g_Wch[(size_t)i0 * NH + tid] = p0.x;
            g_Wcl[(size_t)i0 * NH + tid] = p0.y;
            g_Wch[(size_t)(i0 + 1) * NH + tid] = p1.x;
            g_Wcl[(size_t)(i0 + 1) * NH + tid] = p1.y;
        }
        if (tid < 2) {
            float a0 = 0.f, a1 = 0.f, a2 = 0.f, a3 = 0.f;
            for (int j = 0; j < 512; j += 4) {
                const float4 b4 = *(const float4*)(b_lin + j);
                const float4 x4 = *(const float4*)(s + tid * 512 + j);
                a0 += x4.x * b4.x; a1 += x4.y * b4.y;
                a2 += x4.z * b4.z; a3 += x4.w * b4.w;
            }
            g_bc[i0 + tid] = b_ssp[i0 + tid] + (a0 + a1) + (a2 + a3);
        }
    } else {
        // ---- W3: fused step weights ----
        for (int j = tid; j < 136; j += 128) {
            if (j < 128) {
                float mkbt = 0.f;
                #pragma unroll
                for (int o = 0; o < 6; o++) mkbt += mk[j * 6 + o] * BT[o];
                for (int k = 0; k < 128; k++) {
                    const __nv_bfloat162 p = split_bf(hk[j * 128 + k] + mkbt * he[k]);
                    g_W3h[j * 144 + k] = p.x; g_W3l[j * 144 + k] = p.y;
                }
                #pragma unroll
                for (int p = 0; p < 6; p++) {
                    float sv = mkbt * me[p];
                    #pragma unroll
                    for (int o = 0; o < 6; o++)
                        sv += mk[j * 6 + o] * ((o == p ? 1.f : 0.f) + AT[o * 6 + p]);
                    const __nv_bfloat162 q = split_bf(sv);
                    g_W3h[j * 144 + 128 + p] = q.x; g_W3l[j * 144 + 128 + p] = q.y;
                }
                const __nv_bfloat162 q0 = split_bf(ik[j * 2 + 0] + mkbt * ie[0]);
                const __nv_bfloat162 q1 = split_bf(ik[j * 2 + 1] + mkbt * ie[1]);
                g_W3h[j * 144 + 134] = q0.x; g_W3l[j * 144 + 134] = q0.y;
                g_W3h[j * 144 + 135] = q1.x; g_W3l[j * 144 + 135] = q1.y;
            } else {
                const int o = j - 128;
                const float bt = BT[o];
                for (int k = 0; k < 128; k++) {
                    const __nv_bfloat162 p = split_bf(bt * he[k]);
                    g_W3h[j * 144 + k] = p.x; g_W3l[j * 144 + k] = p.y;
                }
                #pragma unroll
                for (int p = 0; p < 6; p++) {
                    const __nv_bfloat162 q =
                        split_bf((o == p ? 1.f : 0.f) + AT[o * 6 + p] + bt * me[p]);
                    g_W3h[j * 144 + 128 + p] = q.x; g_W3l[j * 144 + 128 + p] = q.y;
                }
                const __nv_bfloat162 q0 = split_bf(bt * ie[0]);
                const __nv_bfloat162 q1 = split_bf(bt * ie[1]);
                g_W3h[j * 144 + 134] = q0.x; g_W3l[j * 144 + 134] = q0.y;
                g_W3h[j * 144 + 135] = q1.x; g_W3l[j * 144 + 135] = q1.y;
            }
            for (int k = 136; k < 144; k++) {
                g_W3h[j * 144 + k] = __float2bfloat16(0.f);
                g_W3l[j * 144 + k] = __float2bfloat16(0.f);
            }
        }
    }
}

// ---------------------------------------------------------------------------
// Kernel 2: recurrence — tensor-core step, 3 accumulator chains (hh/lh/hl)
// ---------------------------------------------------------------------------
__global__ void __launch_bounds__(544) k_recur(const float* __restrict__ vel) {
    __shared__ __align__(16) unsigned char s_xb[19456]; // 2 bufs x 2 planes x 16 x 304B
    __shared__ float s_v[3200];                         // [100][16][2]
    const int tid = threadIdx.x;
    const int b0 = blockIdx.x * 16;
    const u32 xb = smem_u32(s_xb);

    for (int i = tid; i < 19456 / 4; i += 544) ((u32*)s_xb)[i] = 0;
    for (int i = tid; i < 3200; i += 544)
        s_v[i] = vel[(size_t)(i >> 5) * (BATCH * 2) + b0 * 2 + (i & 31)];
    __syncthreads();

    for (int i = tid; i < 2048; i += 544) {
        const int r = i >> 7, c = i & 127;
        const __nv_bfloat162 p = split_bf(g_h0[(size_t)(b0 + r) * NH + c]);
        *(__nv_bfloat16*)(s_xb + r * 304 + c * 2) = p.x;
        *(__nv_bfloat16*)(s_xb + 4864 + r * 304 + c * 2) = p.y;
    }
    for (int i = tid; i < 96; i += 544) {
        const int r = i / 6, o = i % 6;
        const __nv_bfloat162 p = split_bf(g_m0[(size_t)(b0 + r) * NORD + o]);
        *(__nv_bfloat16*)(s_xb + r * 304 + (128 + o) * 2) = p.x;
        *(__nv_bfloat16*)(s_xb + 4864 + r * 304 + (128 + o) * 2) = p.y;
    }
    for (int i = tid; i < 32; i += 544) {
        const int r = i >> 1, c = i & 1;
        const __nv_bfloat162 p = split_bf(s_v[r * 2 + c]);
        *(__nv_bfloat16*)(s_xb + r * 304 + (134 + c) * 2) = p.x;
        *(__nv_bfloat16*)(s_xb + 4864 + r * 304 + (134 + c) * 2) = p.y;
    }

    const int lane = tid & 31, w = tid >> 5;
    const int colB = 8 * w + (lane >> 2);
    u32 bh[9][2], bl[9][2];
    #pragma unroll
    for (int ks = 0; ks < 9; ks++) {
        #pragma unroll
        for (int rr = 0; rr < 2; rr++) {
            const int k0 = ks * 16 + 2 * (lane & 3) + rr * 8;
            bh[ks][rr] = *(const u32*)(g_W3h + colB * 144 + k0);
            bl[ks][rr] = *(const u32*)(g_W3l + colB * 144 + k0);
        }
    }
    __syncthreads();

    const int r0 = lane >> 2;
    const int c0 = 8 * w + 2 * (lane & 3);
    const u32 a_off = (u32)((lane & 15) * 304 + (lane >> 4) * 16);

    #pragma unroll 1
    for (int t = 0; t < T_STEPS; t++) {
        const u32 xro = (u32)(t & 1) * 9728;
        const u32 xwo = xro ^ 9728;
        float a_hh[4] = {0.f, 0.f, 0.f, 0.f};
        float a_lh[4] = {0.f, 0.f, 0.f, 0.f};
        float a_hl[4] = {0.f, 0.f, 0.f, 0.f};

        #pragma unroll
        for (int ks = 0; ks < 9; ks++) {
            u32 ah[4], al[4];
            ldsm4(ah, xb + xro + a_off + ks * 32);
            ldsm4(al, xb + xro + 4864 + a_off + ks * 32);
            mma16816(a_hh, ah, bh[ks]);
            mma16816(a_lh, al, bh[ks]);
            mma16816(a_hl, ah, bl[ks]);
        }
        float acc[4];
        #pragma unroll
        for (int i = 0; i < 4; i++) acc[i] = a_hh[i] + (a_lh[i] + a_hl[i]);

        if (c0 < 128) {
            float hv[4];
            #pragma unroll
            for (int i = 0; i < 4; i++) {
                const float e = __expf(2.f * acc[i]);
                hv[i] = 1.f - __fdividef(2.f, e + 1.f);
            }
            const __nv_bfloat162 s00 = split_bf(hv[0]), s01 = split_bf(hv[1]);
            const __nv_bfloat162 s10 = split_bf(hv[2]), s11 = split_bf(hv[3]);
            const u32 h0h = us(s00.x) | (us(s01.x) << 16);
            const u32 h0l = us(s00.y) | (us(s01.y) << 16);
            const u32 h1h = us(s10.x) | (us(s11.x) << 16);
            const u32 h1l = us(s10.y) | (us(s11.y) << 16);
            *(u32*)(s_xb + xwo + r0 * 304 + c0 * 2)              = h0h;
            *(u32*)(s_xb + xwo + 4864 + r0 * 304 + c0 * 2)       = h0l;
            *(u32*)(s_xb + xwo + (r0 + 8) * 304 + c0 * 2)        = h1h;
            *(u32*)(s_xb + xwo + 4864 + (r0 + 8) * 304 + c0 * 2) = h1l;
            const size_t go = ((size_t)t * BATCH + b0 + r0) * NH + c0;
            *(u32*)(g_Hh + go) = h0h;
            *(u32*)(g_Hl + go) = h0l;
            *(u32*)(g_Hh + go + 8 * NH) = h1h;
            *(u32*)(g_Hl + go + 8 * NH) = h1l;
        } else if (c0 < 134) {
            const __nv_bfloat162 s00 = split_bf(acc[0]), s01 = split_bf(acc[1]);
            const __nv_bfloat162 s10 = split_bf(acc[2]), s11 = split_bf(acc[3]);
            *(u32*)(s_xb + xwo + r0 * 304 + c0 * 2)        = us(s00.x) | (us(s01.x) << 16);
            *(u32*)(s_xb + xwo + 4864 + r0 * 304 + c0 * 2) = us(s00.y) | (us(s01.y) << 16);
            *(u32*)(s_xb + xwo + (r0 + 8) * 304 + c0 * 2)        = us(s10.x) | (us(s11.x) << 16);
            *(u32*)(s_xb + xwo + 4864 + (r0 + 8) * 304 + c0 * 2) = us(s10.y) | (us(s11.y) << 16);
        } else if (t < T_STEPS - 1) {
            const __nv_bfloat162 a0 = split_bf(s_v[(t + 1) * 32 + r0 * 2]);
            const __nv_bfloat162 a1 = split_bf(s_v[(t + 1) * 32 + r0 * 2 + 1]);
            const __nv_bfloat162 b0s = split_bf(s_v[(t + 1) * 32 + (r0 + 8) * 2]);
            const __nv_bfloat162 b1s = split_bf(s_v[(t + 1) * 32 + (r0 + 8) * 2 + 1]);
            *(u32*)(s_xb + xwo + r0 * 304 + 268)        = us(a0.x) | (us(a1.x) << 16);
            *(u32*)(s_xb + xwo + 4864 + r0 * 304 + 268) = us(a0.y) | (us(a1.y) << 16);
            *(u32*)(s_xb + xwo + (r0 + 8) * 304 + 268)        = us(b0s.x) | (us(b1s.x) << 16);
            *(u32*)(s_xb + xwo + 4864 + (r0 + 8) * 304 + 268) = us(b0s.y) | (us(b1s.y) << 16);
        }
        __syncthreads();
    }
}

// ---------------------------------------------------------------------------
// Kernel 3: projection v3 — persistent B, row-tile loop.
// grid (4, 200): CTA owns col tile (128 cols, B resident 64KB) and loops over
// 8 row tiles, streaming A halves (32KB). SMEM 96KB -> 2 CTAs/SM.
// ---------------------------------------------------------------------------
#define PJ_B_HI 0
#define PJ_B_LO 32768
#define PJ_A_HI 65536
#define PJ_A_LO 81920
#define PJ_SMEM 98304

__global__ void __launch_bounds__(256, 2) k_proj(float* __restrict__ out) {
    extern __shared__ char smc[];
    const u32 sb = smem_u32(smc);
    const int tid = threadIdx.x;
    const int w = tid >> 5, lane = tid & 31;
    const int col0 = blockIdx.x * 128;

    const int wm = w & 1, wn = w >> 1;
    const int mbase = wm * 64, nbase = wn * 32;
    const int arow_l = lane & 15, asel = lane >> 4;
    const int brow_l = ((lane >> 4) << 3) + (lane & 7), bsel = (lane >> 3) & 1;

    // Load B (both K halves, both planes) once
    for (int idx = tid; idx < 2048; idx += 256) {
        const int half = idx >> 10, rem = idx & 1023;
        const int row = rem >> 3, c16 = rem & 7;
        const u32 so = (u32)half * 16384 + (u32)row * 128 + ((u32)((c16 ^ (row & 7)) << 4));
        const size_t gb = (size_t)(col0 + row) * NH + half * 64 + c16 * 8;
        cp16(sb + PJ_B_HI + so, g_Wch + gb);
        cp16(sb + PJ_B_LO + so, g_Wcl + gb);
    }
    asm volatile("cp.async.commit_group;");

    // Bias (hoisted; constant across row tiles)
    const int tq = lane >> 2, tr = lane & 3;
    float2 bias[4];
    #pragma unroll
    for (int nt = 0; nt < 4; nt++)
        bias[nt] = *(const float2*)(g_bc + col0 + nbase + nt * 8 + tr * 2);

    #pragma unroll 1
    for (int tile = 0; tile < 8; tile++) {
        const int row0 = (blockIdx.y * 8 + tile) * 128;
        float acc[4][4][4];
        #pragma unroll
        for (int mt = 0; mt < 4; mt++)
            #pragma unroll
            for (int nt = 0; nt < 4; nt++)
                #pragma unroll
                for (int i = 0; i < 4; i++) acc[mt][nt][i] = 0.f;

        #pragma unroll 1
        for (int half = 0; half < 2; half++) {
            if (tile | half) __syncthreads();   // A-buffer ldsm complete before overwrite
            for (int idx = tid; idx < 1024; idx += 256) {
                const int row = idx >> 3, c16 = idx & 7;
                const u32 so = (u32)row * 128 + ((u32)((c16 ^ (row & 7)) << 4));
                const size_t ga = (size_t)(row0 + row) * NH + half * 64 + c16 * 8;
                cp16(sb + PJ_A_HI + so, g_Hh + ga);
                cp16(sb + PJ_A_LO + so, g_Hl + ga);
            }
            asm volatile("cp.async.commit_group;");
            asm volatile("cp.async.wait_group 0;");
            __syncthreads();

            const u32 bb = sb + (u32)half * 16384;
            #pragma unroll
            for (int kk = 0; kk < 4; kk++) {
                u32 ahi[4][4], alo[4][4];
                #pragma unroll
                for (int mt = 0; mt < 4; mt++) {
                    const int row = mbase + mt * 16 + arow_l;
                    const u32 off = (u32)row * 128 + ((u32)(((2 * kk + asel) ^ (row & 7)) << 4));
                    ldsm4(ahi[mt], sb + PJ_A_HI + off);
                    ldsm4(alo[mt], sb + PJ_A_LO + off);
                }
                u32 bhi[2][4], blo[2][4];
                #pragma unroll
                for (int np = 0; np < 2; np++) {
                    const int row = nbase + np * 16 + brow_l;
                    const u32 off = (u32)row * 128 + ((u32)(((2 * kk + bsel) ^ (row & 7)) << 4));
                    ldsm4(bhi[np], bb + PJ_B_HI + off);
                    ldsm4(blo[np], bb + PJ_B_LO + off);
                }
                #pragma unroll
                for (int mt = 0; mt < 4; mt++) {
                    #pragma unroll
                    for (int nt = 0; nt < 4; nt++) {
                        const u32* bhf = &bhi[nt >> 1][(nt & 1) * 2];
                        const u32* blf = &blo[nt >> 1][(nt & 1) * 2];
                        mma16816(acc[mt][nt], ahi[mt], bhf);
                        mma16816(acc[mt][nt], alo[mt], bhf);
                        mma16816(acc[mt][nt], ahi[mt], blf);
                    }
                }
            }
        }

        #pragma unroll
        for (int nt = 0; nt < 4; nt++) {
            const int ncol = col0 + nbase + nt * 8 + tr * 2;
            #pragma unroll
            for (int mt = 0; mt < 4; mt++) {
                const int mrow = row0 + mbase + mt * 16 + tq;
                float2 v0, v1;
                v0.x = acc[mt][nt][0] + bias[nt].x; v0.y = acc[mt][nt][1] + bias[nt].y;
                v1.x = acc[mt][nt][2] + bias[nt].x; v1.y = acc[mt][nt][3] + bias[nt].y;
                *(float2*)(out + (size_t)mrow * NSP + ncol) = v0;
                *(float2*)(out + (size_t)(mrow + 8) * NSP + ncol) = v1;
            }
        }
    }
}

// ---------------------------------------------------------------------------
extern "C" void kernel_launch(void* const* d_in, const int* in_sizes, int n_in,
                              void* d_out, int out_size) {
    const float* vel   = (const float*)d_in[0];
    const float* ssp0  = (const float*)d_in[1];
    const float* ie    = (const float*)d_in[2];
    const float* he    = (const float*)d_in[3];
    const float* me    = (const float*)d_in[4];
    const float* ik    = (const float*)d_in[5];
    const float* hk    = (const float*)d_in[6];
    const float* mk    = (const float*)d_in[7];
    const float* AT    = (const float*)d_in[8];
    const float* BT    = (const float*)d_in[9];
    const float* w_c   = (const float*)d_in[10];
    const float* w_h   = (const float*)d_in[11];
    const float* W_lin = (const float*)d_in[12];
    const float* b_lin = (const float*)d_in[13];
    const float* W_ssp = (const float*)d_in[14];
    const float* b_ssp = (const float*)d_in[15];
    float* out = (float*)d_out;

    const int init_smem = (4096 + 128 * 68) * 4;   // 51200 B
    cudaFuncSetAttribute(k_init, cudaFuncAttributeMaxDynamicSharedMemorySize, init_smem);
    cudaFuncSetAttribute(k_proj, cudaFuncAttributeMaxDynamicSharedMemorySize, PJ_SMEM);

    k_init<<<513, 128, init_smem>>>(ssp0, w_c, w_h, W_lin, b_lin, W_ssp, b_ssp,
                                    he, me, ie, ik, hk, mk, AT, BT);
    k_recur<<<128, 544>>>(vel);
    dim3 g(4, 200);
    k_proj<<<g, 256, PJ_SMEM>>>(out);
}

// round 11
// speedup vs baseline: 1.3070x; 1.3070x over previous
#include <cuda_runtime.h>
#include <cuda_bf16.h>
#include <cuda_fp16.h>

#define T_STEPS 100
#define BATCH   2048
#define NH      128
#define NORD    6
#define NSP     512

typedef unsigned long long ull;
typedef unsigned int u32;

// Scratch (device globals — no allocations allowed).
__device__ __align__(16) __half g_Hf[(size_t)T_STEPS * BATCH * NH];  // fp16 h (single plane)
__device__ __align__(16) float g_h0[BATCH * NH];
__device__ __align__(16) float g_m0[BATCH * NORD];
__device__ __align__(16) __half g_Wph[NSP * NH];                     // Wc fp16 hi
__device__ __align__(16) __half g_Wpl[NSP * NH];                     // Wc fp16 lo
__device__ __align__(16) float g_bc[NSP];
__device__ __align__(16) __nv_bfloat16 g_W3h[136 * 144];
__device__ __align__(16) __nv_bfloat16 g_W3l[136 * 144];

__device__ __forceinline__ void ffma2(ull &d, ull a, ull b) {
    asm("fma.rn.f32x2 %0, %1, %2, %0;" : "+l"(d) : "l"(a), "l"(b));
}
__device__ __forceinline__ float sum2(ull a) {
    float lo, hi;
    asm("mov.b64 {%0,%1}, %2;" : "=f"(lo), "=f"(hi) : "l"(a));
    return lo + hi;
}
__device__ __forceinline__ u32 smem_u32(const void* p) {
    u32 a;
    asm("{ .reg .u64 t; cvta.to.shared.u64 t, %1; cvt.u32.u64 %0, t; }" : "=r"(a) : "l"(p));
    return a;
}
__device__ __forceinline__ __nv_bfloat162 split_bf(float x) {
    __nv_bfloat16 hi = __float2bfloat16(x);
    __nv_bfloat16 lo = __float2bfloat16(x - __bfloat162float(hi));
    __nv_bfloat162 r; r.x = hi; r.y = lo; return r;
}
__device__ __forceinline__ u32 us(__nv_bfloat16 b) {
    return (u32)__bfloat16_as_ushort(b);
}
__device__ __forceinline__ u32 uh(__half h) {
    return (u32)__half_as_ushort(h);
}
__device__ __forceinline__ void ldsm4(u32* r, u32 addr) {
    asm volatile("ldmatrix.sync.aligned.m8n8.x4.shared.b16 {%0,%1,%2,%3}, [%4];"
        : "=r"(r[0]), "=r"(r[1]), "=r"(r[2]), "=r"(r[3]) : "r"(addr));
}
__device__ __forceinline__ void mma16816(float* c, const u32* a, const u32* b) {
    asm volatile(
        "mma.sync.aligned.m16n8k16.row.col.f32.bf16.bf16.f32 "
        "{%0,%1,%2,%3}, {%4,%5,%6,%7}, {%8,%9}, {%0,%1,%2,%3};"
        : "+f"(c[0]), "+f"(c[1]), "+f"(c[2]), "+f"(c[3])
        : "r"(a[0]), "r"(a[1]), "r"(a[2]), "r"(a[3]), "r"(b[0]), "r"(b[1]));
}
__device__ __forceinline__ void mma16816h(float* c, const u32* a, const u32* b) {
    asm volatile(
        "mma.sync.aligned.m16n8k16.row.col.f32.f16.f16.f32 "
        "{%0,%1,%2,%3}, {%4,%5,%6,%7}, {%8,%9}, {%0,%1,%2,%3};"
        : "+f"(c[0]), "+f"(c[1]), "+f"(c[2]), "+f"(c[3])
        : "r"(a[0]), "r"(a[1]), "r"(a[2]), "r"(a[3]), "r"(b[0]), "r"(b[1]));
}
__device__ __forceinline__ void cp16(u32 s, const void* g) {
    asm volatile("cp.async.cg.shared.global [%0], [%1], 16;" :: "r"(s), "l"(g));
}

// ---------------------------------------------------------------------------
// Kernel 1 (merged init): grid 513, dynamic smem 50KB.
// ---------------------------------------------------------------------------
__global__ void __launch_bounds__(128) k_init(
    const float* __restrict__ ssp,   const float* __restrict__ w_c,
    const float* __restrict__ w_h,   const float* __restrict__ W_lin,
    const float* __restrict__ b_lin, const float* __restrict__ W_ssp,
    const float* __restrict__ b_ssp, const float* __restrict__ he,
    const float* __restrict__ me,    const float* __restrict__ ie,
    const float* __restrict__ ik,    const float* __restrict__ hk,
    const float* __restrict__ mk,    const float* __restrict__ AT,
    const float* __restrict__ BT) {
    extern __shared__ float s[];        // setup: ssp 8x512 | w_h tile 128x68
    float* s_ssp = s;
    float* s_wh  = s + 4096;
    const int tid = threadIdx.x;
    const int bid = blockIdx.x;

    if (bid < 256) {
        // ---- setup: h0, m0 for 8 batch rows. w_h staged per 64-K tile ----
        const int b0 = bid * 8;
        for (int i = tid; i < 1024; i += 128)
            ((float4*)s_ssp)[i] = ((const float4*)(ssp + (size_t)b0 * 512))[i];

        ull acc[8];
        #pragma unroll
        for (int r = 0; r < 8; r++) acc[r] = 0ull;

        #pragma unroll 1
        for (int kt = 0; kt < 8; kt++) {
            __syncthreads();
            for (int i = tid; i < 2048; i += 128) {
                const int row = i >> 4, c4 = i & 15;
                const float4 v = *(const float4*)(w_h + row * 512 + kt * 64 + c4 * 4);
                *(float4*)(s_wh + row * 68 + c4 * 4) = v;
            }
            __syncthreads();
            #pragma unroll 4
            for (int c4 = 0; c4 < 16; c4++) {
                const ulonglong2 wp = *(const ulonglong2*)(s_wh + tid * 68 + c4 * 4);
                #pragma unroll
                for (int r = 0; r < 8; r++) {
                    const ulonglong2 xp =
                        *(const ulonglong2*)(s_ssp + r * 512 + kt * 64 + c4 * 4);
                    ffma2(acc[r], xp.x, wp.x);
                    ffma2(acc[r], xp.y, wp.y);
                }
            }
        }
        #pragma unroll
        for (int r = 0; r < 8; r++) g_h0[(size_t)(b0 + r) * NH + tid] = sum2(acc[r]);

        if (tid < 48) {
            const int o = tid >> 3, r = tid & 7;
            const float* wc = w_c + o * 512;
            float a0 = 0.f, a1 = 0.f, a2 = 0.f, a3 = 0.f;
            for (int k = 0; k < 512; k += 4) {
                const float4 w4 = *(const float4*)(wc + k);
                const float4 x4 = *(const float4*)(s_ssp + r * 512 + k);
                a0 += x4.x * w4.x; a1 += x4.y * w4.y;
                a2 += x4.z * w4.z; a3 += x4.w * w4.w;
            }
            g_m0[(size_t)(b0 + r) * NORD + o] = (a0 + a1) + (a2 + a3);
        }
    } else if (bid < 512) {
        // ---- combine: 2 output rows of Wc (fp16 split planes) ----
        const int i0 = (bid - 256) * 2;
        for (int i = tid; i < 2 * 512; i += 128) s[i] = W_ssp[(size_t)i0 * 512 + i];
        __syncthreads();
        float acc0 = 0.f, acc1 = 0.f;
        for (int j = 0; j < 512; j++) {
            const float wl = W_lin[j * 128 + tid];
            acc0 += s[j] * wl;
            acc1 += s[512 + j] * wl;
        }
        {
            const __half h0 = __float2half_rn(acc0);
            const __half l0 = __float2half_rn(acc0 - __half2float(h0));
            const __half h1 = __float2half_rn(acc1);
            const __half l1 = __float2half_rn(acc1 - __half2float(h1));
            g_Wph[(size_t)i0 * NH + tid] = h0;
            g_Wpl[(size_t)i0 * NH + tid] = l0;
            g_Wph[(size_t)(i0 + 1) * NH + tid] = h1;
            g_Wpl[(size_t)(i0 + 1) * NH + tid] = l1;
        }
        if (tid < 2) {
            float a0 = 0.f, a1 = 0.f, a2 = 0.f, a3 = 0.f;
            for (int j = 0; j < 512; j += 4) {
                const float4 b4 = *(const float4*)(b_lin + j);
                const float4 x4 = *(const float4*)(s + tid * 512 + j);
                a0 += x4.x * b4.x; a1 += x4.y * b4.y;
                a2 += x4.z * b4.z; a3 += x4.w * b4.w;
            }
            g_bc[i0 + tid] = b_ssp[i0 + tid] + (a0 + a1) + (a2 + a3);
        }
    } else {
        // ---- W3: fused step weights ----
        for (int j = tid; j < 136; j += 128) {
            if (j < 128) {
                float mkbt = 0.f;
                #pragma unroll
                for (int o = 0; o < 6; o++) mkbt += mk[j * 6 + o] * BT[o];
                for (int k = 0; k < 128; k++) {
                    const __nv_bfloat162 p = split_bf(hk[j * 128 + k] + mkbt * he[k]);
                    g_W3h[j * 144 + k] = p.x; g_W3l[j * 144 + k] = p.y;
                }
                #pragma unroll
                for (int p = 0; p < 6; p++) {
                    float sv = mkbt * me[p];
                    #pragma unroll
                    for (int o = 0; o < 6; o++)
                        sv += mk[j * 6 + o] * ((o == p ? 1.f : 0.f) + AT[o * 6 + p]);
                    const __nv_bfloat162 q = split_bf(sv);
                    g_W3h[j * 144 + 128 + p] = q.x; g_W3l[j * 144 + 128 + p] = q.y;
                }
                const __nv_bfloat162 q0 = split_bf(ik[j * 2 + 0] + mkbt * ie[0]);
                const __nv_bfloat162 q1 = split_bf(ik[j * 2 + 1] + mkbt * ie[1]);
                g_W3h[j * 144 + 134] = q0.x; g_W3l[j * 144 + 134] = q0.y;
                g_W3h[j * 144 + 135] = q1.x; g_W3l[j * 144 + 135] = q1.y;
            } else {
                const int o = j - 128;
                const float bt = BT[o];
                for (int k = 0; k < 128; k++) {
                    const __nv_bfloat162 p = split_bf(bt * he[k]);
                    g_W3h[j * 144 + k] = p.x; g_W3l[j * 144 + k] = p.y;
                }
                #pragma unroll
                for (int p = 0; p < 6; p++) {
                    const __nv_bfloat162 q =
                        split_bf((o == p ? 1.f : 0.f) + AT[o * 6 + p] + bt * me[p]);
                    g_W3h[j * 144 + 128 + p] = q.x; g_W3l[j * 144 + 128 + p] = q.y;
                }
                const __nv_bfloat162 q0 = split_bf(bt * ie[0]);
                const __nv_bfloat162 q1 = split_bf(bt * ie[1]);
                g_W3h[j * 144 + 134] = q0.x; g_W3l[j * 144 + 134] = q0.y;
                g_W3h[j * 144 + 135] = q1.x; g_W3l[j * 144 + 135] = q1.y;
            }
            for (int k = 136; k < 144; k++) {
                g_W3h[j * 144 + k] = __float2bfloat16(0.f);
                g_W3l[j * 144 + k] = __float2bfloat16(0.f);
            }
        }
    }
}

// ---------------------------------------------------------------------------
// Kernel 2: recurrence — tensor-core step (3 chains), fp16 h output plane
// ---------------------------------------------------------------------------
__global__ void __launch_bounds__(544) k_recur(const float* __restrict__ vel) {
    __shared__ __align__(16) unsigned char s_xb[19456]; // 2 bufs x 2 planes x 16 x 304B
    __shared__ float s_v[3200];                         // [100][16][2]
    const int tid = threadIdx.x;
    const int b0 = blockIdx.x * 16;
    const u32 xb = smem_u32(s_xb);

    for (int i = tid; i < 19456 / 4; i += 544) ((u32*)s_xb)[i] = 0;
    for (int i = tid; i < 3200; i += 544)
        s_v[i] = vel[(size_t)(i >> 5) * (BATCH * 2) + b0 * 2 + (i & 31)];
    __syncthreads();

    for (int i = tid; i < 2048; i += 544) {
        const int r = i >> 7, c = i & 127;
        const __nv_bfloat162 p = split_bf(g_h0[(size_t)(b0 + r) * NH + c]);
        *(__nv_bfloat16*)(s_xb + r * 304 + c * 2) = p.x;
        *(__nv_bfloat16*)(s_xb + 4864 + r * 304 + c * 2) = p.y;
    }
    for (int i = tid; i < 96; i += 544) {
        const int r = i / 6, o = i % 6;
        const __nv_bfloat162 p = split_bf(g_m0[(size_t)(b0 + r) * NORD + o]);
        *(__nv_bfloat16*)(s_xb + r * 304 + (128 + o) * 2) = p.x;
        *(__nv_bfloat16*)(s_xb + 4864 + r * 304 + (128 + o) * 2) = p.y;
    }
    for (int i = tid; i < 32; i += 544) {
        const int r = i >> 1, c = i & 1;
        const __nv_bfloat162 p = split_bf(s_v[r * 2 + c]);
        *(__nv_bfloat16*)(s_xb + r * 304 + (134 + c) * 2) = p.x;
        *(__nv_bfloat16*)(s_xb + 4864 + r * 304 + (134 + c) * 2) = p.y;
    }

    const int lane = tid & 31, w = tid >> 5;
    const int colB = 8 * w + (lane >> 2);
    u32 bh[9][2], bl[9][2];
    #pragma unroll
    for (int ks = 0; ks < 9; ks++) {
        #pragma unroll
        for (int rr = 0; rr < 2; rr++) {
            const int k0 = ks * 16 + 2 * (lane & 3) + rr * 8;
            bh[ks][rr] = *(const u32*)(g_W3h + colB * 144 + k0);
            bl[ks][rr] = *(const u32*)(g_W3l + colB * 144 + k0);
        }
    }
    __syncthreads();

    const int r0 = lane >> 2;
    const int c0 = 8 * w + 2 * (lane & 3);
    const u32 a_off = (u32)((lane & 15) * 304 + (lane >> 4) * 16);

    #pragma unroll 1
    for (int t = 0; t < T_STEPS; t++) {
        const u32 xro = (u32)(t & 1) * 9728;
        const u32 xwo = xro ^ 9728;
        float a_hh[4] = {0.f, 0.f, 0.f, 0.f};
        float a_lh[4] = {0.f, 0.f, 0.f, 0.f};
        float a_hl[4] = {0.f, 0.f, 0.f, 0.f};

        #pragma unroll
        for (int ks = 0; ks < 9; ks++) {
            u32 ah[4], al[4];
            ldsm4(ah, xb + xro + a_off + ks * 32);
            ldsm4(al, xb + xro + 4864 + a_off + ks * 32);
            mma16816(a_hh, ah, bh[ks]);
            mma16816(a_lh, al, bh[ks]);
            mma16816(a_hl, ah, bl[ks]);
        }
        float acc[4];
        #pragma unroll
        for (int i = 0; i < 4; i++) acc[i] = a_hh[i] + (a_lh[i] + a_hl[i]);

        if (c0 < 128) {
            float hv[4];
            #pragma unroll
            for (int i = 0; i < 4; i++) {
                const float e = __expf(2.f * acc[i]);
                hv[i] = 1.f - __fdividef(2.f, e + 1.f);
            }
            const __nv_bfloat162 s00 = split_bf(hv[0]), s01 = split_bf(hv[1]);
            const __nv_bfloat162 s10 = split_bf(hv[2]), s11 = split_bf(hv[3]);
            *(u32*)(s_xb + xwo + r0 * 304 + c0 * 2)              = us(s00.x) | (us(s01.x) << 16);
            *(u32*)(s_xb + xwo + 4864 + r0 * 304 + c0 * 2)       = us(s00.y) | (us(s01.y) << 16);
            *(u32*)(s_xb + xwo + (r0 + 8) * 304 + c0 * 2)        = us(s10.x) | (us(s11.x) << 16);
            *(u32*)(s_xb + xwo + 4864 + (r0 + 8) * 304 + c0 * 2) = us(s10.y) | (us(s11.y) << 16);
            const size_t go = ((size_t)t * BATCH + b0 + r0) * NH + c0;
            *(u32*)(g_Hf + go) =
                uh(__float2half_rn(hv[0])) | (uh(__float2half_rn(hv[1])) << 16);
            *(u32*)(g_Hf + go + 8 * NH) =
                uh(__float2half_rn(hv[2])) | (uh(__float2half_rn(hv[3])) << 16);
        } else if (c0 < 134) {
            const __nv_bfloat162 s00 = split_bf(acc[0]), s01 = split_bf(acc[1]);
            const __nv_bfloat162 s10 = split_bf(acc[2]), s11 = split_bf(acc[3]);
            *(u32*)(s_xb + xwo + r0 * 304 + c0 * 2)        = us(s00.x) | (us(s01.x) << 16);
            *(u32*)(s_xb + xwo + 4864 + r0 * 304 + c0 * 2) = us(s00.y) | (us(s01.y) << 16);
            *(u32*)(s_xb + xwo + (r0 + 8) * 304 + c0 * 2)        = us(s10.x) | (us(s11.x) << 16);
            *(u32*)(s_xb + xwo + 4864 + (r0 + 8) * 304 + c0 * 2) = us(s10.y) | (us(s11.y) << 16);
        } else if (t < T_STEPS - 1) {
            const __nv_bfloat162 a0 = split_bf(s_v[(t + 1) * 32 + r0 * 2]);
            const __nv_bfloat162 a1 = split_bf(s_v[(t + 1) * 32 + r0 * 2 + 1]);
            const __nv_bfloat162 b0s = split_bf(s_v[(t + 1) * 32 + (r0 + 8) * 2]);
            const __nv_bfloat162 b1s = split_bf(s_v[(t + 1) * 32 + (r0 + 8) * 2 + 1]);
            *(u32*)(s_xb + xwo + r0 * 304 + 268)        = us(a0.x) | (us(a1.x) << 16);
            *(u32*)(s_xb + xwo + 4864 + r0 * 304 + 268) = us(a0.y) | (us(a1.y) << 16);
            *(u32*)(s_xb + xwo + (r0 + 8) * 304 + 268)        = us(b0s.x) | (us(b1s.x) << 16);
            *(u32*)(s_xb + xwo + 4864 + (r0 + 8) * 304 + 268) = us(b0s.y) | (us(b1s.y) << 16);
        }
        __syncthreads();
    }
}

// ---------------------------------------------------------------------------
// Kernel 3: projection v4 — fp16 asymmetric 2-pass HMMA.
// C = A(fp16) @ (B_hi + B_lo)^T + bc. CTA 128x128, full K resident.
// SMEM: A 32KB | B_hi 32KB | B_lo 32KB = 96KB -> 2 CTAs/SM. Rows 256B,
// swizzle (c16 ^ (row&7))<<4 — conflict-free stores and ldsm phases.
// ---------------------------------------------------------------------------
#define PJ_A  0
#define PJ_BH 32768
#define PJ_BL 65536
#define PJ_SMEM 98304

__global__ void __launch_bounds__(256, 2) k_proj(float* __restrict__ out) {
    extern __shared__ char smc[];
    const u32 sb = smem_u32(smc);
    const int tid = threadIdx.x;
    const int w = tid >> 5, lane = tid & 31;
    const int col0 = blockIdx.x * 128;
    const int row0 = blockIdx.y * 128;

    const int wm = w & 1, wn = w >> 1;
    const int mbase = wm * 64, nbase = wn * 32;
    const int arow_l = lane & 15, asel = lane >> 4;
    const int brow_l = ((lane >> 4) << 3) + (lane & 7), bsel = (lane >> 3) & 1;

    // Single-shot load: A (128x128 fp16) + B hi/lo
    for (int idx = tid; idx < 2048; idx += 256) {
        const int row = idx >> 4, c16 = idx & 15;
        const u32 so = (u32)row * 256 + ((u32)((c16 ^ (row & 7)) << 4));
        cp16(sb + PJ_A + so, g_Hf + (size_t)(row0 + row) * NH + c16 * 8);
        const size_t gb = (size_t)(col0 + row) * NH + c16 * 8;
        cp16(sb + PJ_BH + so, g_Wph + gb);
        cp16(sb + PJ_BL + so, g_Wpl + gb);
    }
    asm volatile("cp.async.commit_group;");
    asm volatile("cp.async.wait_group 0;");
    __syncthreads();

    float acc[4][4][4];
    #pragma unroll
    for (int mt = 0; mt < 4; mt++)
        #pragma unroll
        for (int nt = 0; nt < 4; nt++)
            #pragma unroll
            for (int i = 0; i < 4; i++) acc[mt][nt][i] = 0.f;

    #pragma unroll
    for (int kk = 0; kk < 8; kk++) {
        u32 a[4][4];
        #pragma unroll
        for (int mt = 0; mt < 4; mt++) {
            const int row = mbase + mt * 16 + arow_l;
            const u32 off = (u32)row * 256 + ((u32)(((2 * kk + asel) ^ (row & 7)) << 4));
            ldsm4(a[mt], sb + PJ_A + off);
        }
        u32 bhi[2][4], blo[2][4];
        #pragma unroll
        for (int np = 0; np < 2; np++) {
            const int row = nbase + np * 16 + brow_l;
            const u32 off = (u32)row * 256 + ((u32)(((2 * kk + bsel) ^ (row & 7)) << 4));
            ldsm4(bhi[np], sb + PJ_BH + off);
            ldsm4(blo[np], sb + PJ_BL + off);
        }
        #pragma unroll
        for (int mt = 0; mt < 4; mt++) {
            #pragma unroll
            for (int nt = 0; nt < 4; nt++) {
                const u32* bhf = &bhi[nt >> 1][(nt & 1) * 2];
                const u32* blf = &blo[nt >> 1][(nt & 1) * 2];
                mma16816h(acc[mt][nt], a[mt], bhf);
                mma16816h(acc[mt][nt], a[mt], blf);
            }
        }
    }

    const int tq = lane >> 2, tr = lane & 3;
    #pragma unroll
    for (int nt = 0; nt < 4; nt++) {
        const int ncol = col0 + nbase + nt * 8 + tr * 2;
        const float2 bias = *(const float2*)(g_bc + ncol);
        #pragma unroll
        for (int mt = 0; mt < 4; mt++) {
            const int mrow = row0 + mbase + mt * 16 + tq;
            float2 v0, v1;
            v0.x = acc[mt][nt][0] + bias.x; v0.y = acc[mt][nt][1] + bias.y;
            v1.x = acc[mt][nt][2] + bias.x; v1.y = acc[mt][nt][3] + bias.y;
            *(float2*)(out + (size_t)mrow * NSP + ncol) = v0;
            *(float2*)(out + (size_t)(mrow + 8) * NSP + ncol) = v1;
        }
    }
}

// ---------------------------------------------------------------------------
extern "C" void kernel_launch(void* const* d_in, const int* in_sizes, int n_in,
                              void* d_out, int out_size) {
    const float* vel   = (const float*)d_in[0];
    const float* ssp0  = (const float*)d_in[1];
    const float* ie    = (const float*)d_in[2];
    const float* he    = (const float*)d_in[3];
    const float* me    = (const float*)d_in[4];
    const float* ik    = (const float*)d_in[5];
    const float* hk    = (const float*)d_in[6];
    const float* mk    = (const float*)d_in[7];
    const float* AT    = (const float*)d_in[8];
    const float* BT    = (const float*)d_in[9];
    const float* w_c   = (const float*)d_in[10];
    const float* w_h   = (const float*)d_in[11];
    const float* W_lin = (const float*)d_in[12];
    const float* b_lin = (const float*)d_in[13];
    const float* W_ssp = (const float*)d_in[14];
    const float* b_ssp = (const float*)d_in[15];
    float* out = (float*)d_out;

    const int init_smem = (4096 + 128 * 68) * 4;   // 51200 B
    cudaFuncSetAttribute(k_init, cudaFuncAttributeMaxDynamicSharedMemorySize, init_smem);
    cudaFuncSetAttribute(k_proj, cudaFuncAttributeMaxDynamicSharedMemorySize, PJ_SMEM);

    k_init<<<513, 128, init_smem>>>(ssp0, w_c, w_h, W_lin, b_lin, W_ssp, b_ssp,
                                    he, me, ie, ik, hk, mk, AT, BT);
    k_recur<<<128, 544>>>(vel);
    dim3 g(4, 1600);
    k_proj<<<g, 256, PJ_SMEM>>>(out);
}

// round 12
// speedup vs baseline: 1.3469x; 1.0305x over previous
#include <cuda_runtime.h>
#include <cuda_bf16.h>
#include <cuda_fp16.h>

#define T_STEPS 100
#define BATCH   2048
#define NH      128
#define NORD    6
#define NSP     512

typedef unsigned long long ull;
typedef unsigned int u32;

// Scratch (device globals — no allocations allowed).
__device__ __align__(16) __half g_Hf[(size_t)T_STEPS * BATCH * NH];  // fp16 h (single plane)
__device__ __align__(16) float g_h0[BATCH * NH];
__device__ __align__(16) float g_m0[BATCH * NORD];
__device__ __align__(16) __half g_Wph[NSP * NH];                     // Wc fp16 (single plane)
__device__ __align__(16) float g_bc[NSP];
__device__ __align__(16) __nv_bfloat16 g_W3h[136 * 144];
__device__ __align__(16) __nv_bfloat16 g_W3l[136 * 144];

__device__ __forceinline__ void ffma2(ull &d, ull a, ull b) {
    asm("fma.rn.f32x2 %0, %1, %2, %0;" : "+l"(d) : "l"(a), "l"(b));
}
__device__ __forceinline__ float sum2(ull a) {
    float lo, hi;
    asm("mov.b64 {%0,%1}, %2;" : "=f"(lo), "=f"(hi) : "l"(a));
    return lo + hi;
}
__device__ __forceinline__ u32 smem_u32(const void* p) {
    u32 a;
    asm("{ .reg .u64 t; cvta.to.shared.u64 t, %1; cvt.u32.u64 %0, t; }" : "=r"(a) : "l"(p));
    return a;
}
__device__ __forceinline__ __nv_bfloat162 split_bf(float x) {
    __nv_bfloat16 hi = __float2bfloat16(x);
    __nv_bfloat16 lo = __float2bfloat16(x - __bfloat162float(hi));
    __nv_bfloat162 r; r.x = hi; r.y = lo; return r;
}
__device__ __forceinline__ u32 us(__nv_bfloat16 b) {
    return (u32)__bfloat16_as_ushort(b);
}
__device__ __forceinline__ u32 uh(__half h) {
    return (u32)__half_as_ushort(h);
}
__device__ __forceinline__ void ldsm4(u32* r, u32 addr) {
    asm volatile("ldmatrix.sync.aligned.m8n8.x4.shared.b16 {%0,%1,%2,%3}, [%4];"
        : "=r"(r[0]), "=r"(r[1]), "=r"(r[2]), "=r"(r[3]) : "r"(addr));
}
__device__ __forceinline__ void mma16816(float* c, const u32* a, const u32* b) {
    asm volatile(
        "mma.sync.aligned.m16n8k16.row.col.f32.bf16.bf16.f32 "
        "{%0,%1,%2,%3}, {%4,%5,%6,%7}, {%8,%9}, {%0,%1,%2,%3};"
        : "+f"(c[0]), "+f"(c[1]), "+f"(c[2]), "+f"(c[3])
        : "r"(a[0]), "r"(a[1]), "r"(a[2]), "r"(a[3]), "r"(b[0]), "r"(b[1]));
}
__device__ __forceinline__ void mma16816h(float* c, const u32* a, const u32* b) {
    asm volatile(
        "mma.sync.aligned.m16n8k16.row.col.f32.f16.f16.f32 "
        "{%0,%1,%2,%3}, {%4,%5,%6,%7}, {%8,%9}, {%0,%1,%2,%3};"
        : "+f"(c[0]), "+f"(c[1]), "+f"(c[2]), "+f"(c[3])
        : "r"(a[0]), "r"(a[1]), "r"(a[2]), "r"(a[3]), "r"(b[0]), "r"(b[1]));
}
__device__ __forceinline__ void cp16(u32 s, const void* g) {
    asm volatile("cp.async.cg.shared.global [%0], [%1], 16;" :: "r"(s), "l"(g));
}

// ---------------------------------------------------------------------------
// Kernel 1 (merged init): grid 513, dynamic smem 50KB.
//   blocks [0,256):   m0/h0 setup, 8 batch rows per CTA (tiled, coalesced)
//   blocks [256,512): Wc = W_ssp @ W_lin (fp16) + bc, MLP-split accumulators
//   block  512:       fused step weights W3 (elementwise coalesced)
// ---------------------------------------------------------------------------
__global__ void __launch_bounds__(128) k_init(
    const float* __restrict__ ssp,   const float* __restrict__ w_c,
    const float* __restrict__ w_h,   const float* __restrict__ W_lin,
    const float* __restrict__ b_lin, const float* __restrict__ W_ssp,
    const float* __restrict__ b_ssp, const float* __restrict__ he,
    const float* __restrict__ me,    const float* __restrict__ ie,
    const float* __restrict__ ik,    const float* __restrict__ hk,
    const float* __restrict__ mk,    const float* __restrict__ AT,
    const float* __restrict__ BT) {
    extern __shared__ float s[];        // setup: ssp 8x512 | w_h tile 128x68
    float* s_ssp = s;
    float* s_wh  = s + 4096;
    const int tid = threadIdx.x;
    const int bid = blockIdx.x;

    if (bid < 256) {
        // ---- setup: h0, m0 for 8 batch rows. w_h staged per 64-K tile ----
        const int b0 = bid * 8;
        for (int i = tid; i < 1024; i += 128)
            ((float4*)s_ssp)[i] = ((const float4*)(ssp + (size_t)b0 * 512))[i];

        ull acc[8];
        #pragma unroll
        for (int r = 0; r < 8; r++) acc[r] = 0ull;

        #pragma unroll 1
        for (int kt = 0; kt < 8; kt++) {
            __syncthreads();
            for (int i = tid; i < 2048; i += 128) {
                const int row = i >> 4, c4 = i & 15;
                const float4 v = *(const float4*)(w_h + row * 512 + kt * 64 + c4 * 4);
                *(float4*)(s_wh + row * 68 + c4 * 4) = v;
            }
            __syncthreads();
            #pragma unroll 4
            for (int c4 = 0; c4 < 16; c4++) {
                const ulonglong2 wp = *(const ulonglong2*)(s_wh + tid * 68 + c4 * 4);
                #pragma unroll
                for (int r = 0; r < 8; r++) {
                    const ulonglong2 xp =
                        *(const ulonglong2*)(s_ssp + r * 512 + kt * 64 + c4 * 4);
                    ffma2(acc[r], xp.x, wp.x);
                    ffma2(acc[r], xp.y, wp.y);
                }
            }
        }
        #pragma unroll
        for (int r = 0; r < 8; r++) g_h0[(size_t)(b0 + r) * NH + tid] = sum2(acc[r]);

        if (tid < 48) {
            const int o = tid >> 3, r = tid & 7;
            const float* wc = w_c + o * 512;
            float a0 = 0.f, a1 = 0.f, a2 = 0.f, a3 = 0.f;
            for (int k = 0; k < 512; k += 4) {
                const float4 w4 = *(const float4*)(wc + k);
                const float4 x4 = *(const float4*)(s_ssp + r * 512 + k);
                a0 += x4.x * w4.x; a1 += x4.y * w4.y;
                a2 += x4.z * w4.z; a3 += x4.w * w4.w;
            }
            g_m0[(size_t)(b0 + r) * NORD + o] = (a0 + a1) + (a2 + a3);
        }
    } else if (bid < 512) {
        // ---- combine: 2 output rows of Wc. 4 independent chains -> MLP up ----
        const int i0 = (bid - 256) * 2;
        for (int i = tid; i < 2 * 512; i += 128) s[i] = W_ssp[(size_t)i0 * 512 + i];
        __syncthreads();
        float p0[4] = {0.f, 0.f, 0.f, 0.f};
        float p1[4] = {0.f, 0.f, 0.f, 0.f};
        #pragma unroll 4
        for (int j = 0; j < 512; j += 4) {
            #pragma unroll
            for (int u = 0; u < 4; u++) {
                const float wl = W_lin[(j + u) * 128 + tid];
                p0[u] += s[j + u] * wl;
                p1[u] += s[512 + j + u] * wl;
            }
        }
        const float acc0 = (p0[0] + p0[1]) + (p0[2] + p0[3]);
        const float acc1 = (p1[0] + p1[1]) + (p1[2] + p1[3]);
        g_Wph[(size_t)i0 * NH + tid] = __float2half_rn(acc0);
        g_Wph[(size_t)(i0 + 1) * NH + tid] = __float2half_rn(acc1);
        if (tid < 2) {
            float a0 = 0.f, a1 = 0.f, a2 = 0.f, a3 = 0.f;
            for (int j = 0; j < 512; j += 4) {
                const float4 b4 = *(const float4*)(b_lin + j);
                const float4 x4 = *(const float4*)(s + tid * 512 + j);
                a0 += x4.x * b4.x; a1 += x4.y * b4.y;
                a2 += x4.z * b4.z; a3 += x4.w * b4.w;
            }
            g_bc[i0 + tid] = b_ssp[i0 + tid] + (a0 + a1) + (a2 + a3);
        }
    } else {
        // ---- W3: fused step weights, elementwise coalesced ----
        if (tid < 128) {
            float mb = 0.f;
            #pragma unroll
            for (int o = 0; o < 6; o++) mb += mk[tid * 6 + o] * BT[o];
            s[tid] = mb;   // mkbt[j]
        }
        __syncthreads();
        #pragma unroll 2
        for (int idx = tid; idx < 136 * 144; idx += 128) {
            const int j = idx / 144, k = idx - j * 144;
            float v = 0.f;
            if (j < 128) {
                if (k < 128) {
                    v = hk[j * 128 + k] + s[j] * he[k];
                } else if (k < 134) {
                    const int p = k - 128;
                    v = s[j] * me[p];
                    #pragma unroll
                    for (int o = 0; o < 6; o++)
                        v += mk[j * 6 + o] * ((o == p ? 1.f : 0.f) + AT[o * 6 + p]);
                } else if (k < 136) {
                    v = ik[j * 2 + (k - 134)] + s[j] * ie[k - 134];
                }
            } else if (j < 134) {
                const int o = j - 128;
                const float bt = BT[o];
                if (k < 128) {
                    v = bt * he[k];
                } else if (k < 134) {
                    const int p = k - 128;
                    v = (o == p ? 1.f : 0.f) + AT[o * 6 + p] + bt * me[p];
                } else if (k < 136) {
                    v = bt * ie[k - 134];
                }
            }
            const __nv_bfloat162 q = split_bf(v);
            g_W3h[idx] = q.x;
            g_W3l[idx] = q.y;
        }
    }
}

// ---------------------------------------------------------------------------
// Kernel 2: recurrence — tensor-core step (3 chains), fp16 h output plane
// (unchanged from R11)
// ---------------------------------------------------------------------------
__global__ void __launch_bounds__(544) k_recur(const float* __restrict__ vel) {
    __shared__ __align__(16) unsigned char s_xb[19456]; // 2 bufs x 2 planes x 16 x 304B
    __shared__ float s_v[3200];                         // [100][16][2]
    const int tid = threadIdx.x;
    const int b0 = blockIdx.x * 16;
    const u32 xb = smem_u32(s_xb);

    for (int i = tid; i < 19456 / 4; i += 544) ((u32*)s_xb)[i] = 0;
    for (int i = tid; i < 3200; i += 544)
        s_v[i] = vel[(size_t)(i >> 5) * (BATCH * 2) + b0 * 2 + (i & 31)];
    __syncthreads();

    for (int i = tid; i < 2048; i += 544) {
        const int r = i >> 7, c = i & 127;
        const __nv_bfloat162 p = split_bf(g_h0[(size_t)(b0 + r) * NH + c]);
        *(__nv_bfloat16*)(s_xb + r * 304 + c * 2) = p.x;
        *(__nv_bfloat16*)(s_xb + 4864 + r * 304 + c * 2) = p.y;
    }
    for (int i = tid; i < 96; i += 544) {
        const int r = i / 6, o = i % 6;
        const __nv_bfloat162 p = split_bf(g_m0[(size_t)(b0 + r) * NORD + o]);
        *(__nv_bfloat16*)(s_xb + r * 304 + (128 + o) * 2) = p.x;
        *(__nv_bfloat16*)(s_xb + 4864 + r * 304 + (128 + o) * 2) = p.y;
    }
    for (int i = tid; i < 32; i += 544) {
        const int r = i >> 1, c = i & 1;
        const __nv_bfloat162 p = split_bf(s_v[r * 2 + c]);
        *(__nv_bfloat16*)(s_xb + r * 304 + (134 + c) * 2) = p.x;
        *(__nv_bfloat16*)(s_xb + 4864 + r * 304 + (134 + c) * 2) = p.y;
    }

    const int lane = tid & 31, w = tid >> 5;
    const int colB = 8 * w + (lane >> 2);
    u32 bh[9][2], bl[9][2];
    #pragma unroll
    for (int ks = 0; ks < 9; ks++) {
        #pragma unroll
        for (int rr = 0; rr < 2; rr++) {
            const int k0 = ks * 16 + 2 * (lane & 3) + rr * 8;
            bh[ks][rr] = *(const u32*)(g_W3h + colB * 144 + k0);
            bl[ks][rr] = *(const u32*)(g_W3l + colB * 144 + k0);
        }
    }
    __syncthreads();

    const int r0 = lane >> 2;
    const int c0 = 8 * w + 2 * (lane & 3);
    const u32 a_off = (u32)((lane & 15) * 304 + (lane >> 4) * 16);

    #pragma unroll 1
    for (int t = 0; t < T_STEPS; t++) {
        const u32 xro = (u32)(t & 1) * 9728;
        const u32 xwo = xro ^ 9728;
        float a_hh[4] = {0.f, 0.f, 0.f, 0.f};
        float a_lh[4] = {0.f, 0.f, 0.f, 0.f};
        float a_hl[4] = {0.f, 0.f, 0.f, 0.f};

        #pragma unroll
        for (int ks = 0; ks < 9; ks++) {
            u32 ah[4], al[4];
            ldsm4(ah, xb + xro + a_off + ks * 32);
            ldsm4(al, xb + xro + 4864 + a_off + ks * 32);
            mma16816(a_hh, ah, bh[ks]);
            mma16816(a_lh, al, bh[ks]);
            mma16816(a_hl, ah, bl[ks]);
        }
        float acc[4];
        #pragma unroll
        for (int i = 0; i < 4; i++) acc[i] = a_hh[i] + (a_lh[i] + a_hl[i]);

        if (c0 < 128) {
            float hv[4];
            #pragma unroll
            for (int i = 0; i < 4; i++) {
                const float e = __expf(2.f * acc[i]);
                hv[i] = 1.f - __fdividef(2.f, e + 1.f);
            }
            const __nv_bfloat162 s00 = split_bf(hv[0]), s01 = split_bf(hv[1]);
            const __nv_bfloat162 s10 = split_bf(hv[2]), s11 = split_bf(hv[3]);
            *(u32*)(s_xb + xwo + r0 * 304 + c0 * 2)              = us(s00.x) | (us(s01.x) << 16);
            *(u32*)(s_xb + xwo + 4864 + r0 * 304 + c0 * 2)       = us(s00.y) | (us(s01.y) << 16);
            *(u32*)(s_xb + xwo + (r0 + 8) * 304 + c0 * 2)        = us(s10.x) | (us(s11.x) << 16);
            *(u32*)(s_xb + xwo + 4864 + (r0 + 8) * 304 + c0 * 2) = us(s10.y) | (us(s11.y) << 16);
            const size_t go = ((size_t)t * BATCH + b0 + r0) * NH + c0;
            *(u32*)(g_Hf + go) =
                uh(__float2half_rn(hv[0])) | (uh(__float2half_rn(hv[1])) << 16);
            *(u32*)(g_Hf + go + 8 * NH) =
                uh(__float2half_rn(hv[2])) | (uh(__float2half_rn(hv[3])) << 16);
        } else if (c0 < 134) {
            const __nv_bfloat162 s00 = split_bf(acc[0]), s01 = split_bf(acc[1]);
            const __nv_bfloat162 s10 = split_bf(acc[2]), s11 = split_bf(acc[3]);
            *(u32*)(s_xb + xwo + r0 * 304 + c0 * 2)        = us(s00.x) | (us(s01.x) << 16);
            *(u32*)(s_xb + xwo + 4864 + r0 * 304 + c0 * 2) = us(s00.y) | (us(s01.y) << 16);
            *(u32*)(s_xb + xwo + (r0 + 8) * 304 + c0 * 2)        = us(s10.x) | (us(s11.x) << 16);
            *(u32*)(s_xb + xwo + 4864 + (r0 + 8) * 304 + c0 * 2) = us(s10.y) | (us(s11.y) << 16);
        } else if (t < T_STEPS - 1) {
            const __nv_bfloat162 a0 = split_bf(s_v[(t + 1) * 32 + r0 * 2]);
            const __nv_bfloat162 a1 = split_bf(s_v[(t + 1) * 32 + r0 * 2 + 1]);
            const __nv_bfloat162 b0s = split_bf(s_v[(t + 1) * 32 + (r0 + 8) * 2]);
            const __nv_bfloat162 b1s = split_bf(s_v[(t + 1) * 32 + (r0 + 8) * 2 + 1]);
            *(u32*)(s_xb + xwo + r0 * 304 + 268)        = us(a0.x) | (us(a1.x) << 16);
            *(u32*)(s_xb + xwo + 4864 + r0 * 304 + 268) = us(a0.y) | (us(a1.y) << 16);
            *(u32*)(s_xb + xwo + (r0 + 8) * 304 + 268)        = us(b0s.x) | (us(b1s.x) << 16);
            *(u32*)(s_xb + xwo + 4864 + (r0 + 8) * 304 + 268) = us(b0s.y) | (us(b1s.y) << 16);
        }
        __syncthreads();
    }
}

// ---------------------------------------------------------------------------
// Kernel 3: projection v5 — fp16 single-pass HMMA.
// C = A(fp16) @ B(fp16)^T + bc. CTA 128x128, full K resident, SMEM 64KB.
// ---------------------------------------------------------------------------
#define PJ_A  0
#define PJ_BH 32768
#define PJ_SMEM 65536

__global__ void __launch_bounds__(256, 2) k_proj(float* __restrict__ out) {
    extern __shared__ char smc[];
    const u32 sb = smem_u32(smc);
    const int tid = threadIdx.x;
    const int w = tid >> 5, lane = tid & 31;
    const int col0 = blockIdx.x * 128;
    const int row0 = blockIdx.y * 128;

    const int wm = w & 1, wn = w >> 1;
    const int mbase = wm * 64, nbase = wn * 32;
    const int arow_l = lane & 15, asel = lane >> 4;
    const int brow_l = ((lane >> 4) << 3) + (lane & 7), bsel = (lane >> 3) & 1;

    // Single-shot load: A (128x128 fp16) + B (128x128 fp16)
    for (int idx = tid; idx < 2048; idx += 256) {
        const int row = idx >> 4, c16 = idx & 15;
        const u32 so = (u32)row * 256 + ((u32)((c16 ^ (row & 7)) << 4));
        cp16(sb + PJ_A + so, g_Hf + (size_t)(row0 + row) * NH + c16 * 8);
        cp16(sb + PJ_BH + so, g_Wph + (size_t)(col0 + row) * NH + c16 * 8);
    }
    asm volatile("cp.async.commit_group;");
    asm volatile("cp.async.wait_group 0;");
    __syncthreads();

    float acc[4][4][4];
    #pragma unroll
    for (int mt = 0; mt < 4; mt++)
        #pragma unroll
        for (int nt = 0; nt < 4; nt++)
            #pragma unroll
            for (int i = 0; i < 4; i++) acc[mt][nt][i] = 0.f;

    #pragma unroll
    for (int kk = 0; kk < 8; kk++) {
        u32 a[4][4];
        #pragma unroll
        for (int mt = 0; mt < 4; mt++) {
            const int row = mbase + mt * 16 + arow_l;
            const u32 off = (u32)row * 256 + ((u32)(((2 * kk + asel) ^ (row & 7)) << 4));
            ldsm4(a[mt], sb + PJ_A + off);
        }
        u32 bhi[2][4];
        #pragma unroll
        for (int np = 0; np < 2; np++) {
            const int row = nbase + np * 16 + brow_l;
            const u32 off = (u32)row * 256 + ((u32)(((2 * kk + bsel) ^ (row & 7)) << 4));
            ldsm4(bhi[np], sb + PJ_BH + off);
        }
        #pragma unroll
        for (int mt = 0; mt < 4; mt++) {
            #pragma unroll
            for (int nt = 0; nt < 4; nt++) {
                mma16816h(acc[mt][nt], a[mt], &bhi[nt >> 1][(nt & 1) * 2]);
            }
        }
    }

    const int tq = lane >> 2, tr = lane & 3;
    #pragma unroll
    for (int nt = 0; nt < 4; nt++) {
        const int ncol = col0 + nbase + nt * 8 + tr * 2;
        const float2 bias = *(const float2*)(g_bc + ncol);
        #pragma unroll
        for (int mt = 0; mt < 4; mt++) {
            const int mrow = row0 + mbase + mt * 16 + tq;
            float2 v0, v1;
            v0.x = acc[mt][nt][0] + bias.x; v0.y = acc[mt][nt][1] + bias.y;
            v1.x = acc[mt][nt][2] + bias.x; v1.y = acc[mt][nt][3] + bias.y;
            *(float2*)(out + (size_t)mrow * NSP + ncol) = v0;
            *(float2*)(out + (size_t)(mrow + 8) * NSP + ncol) = v1;
        }
    }
}

// ---------------------------------------------------------------------------
extern "C" void kernel_launch(void* const* d_in, const int* in_sizes, int n_in,
                              void* d_out, int out_size) {
    const float* vel   = (const float*)d_in[0];
    const float* ssp0  = (const float*)d_in[1];
    const float* ie    = (const float*)d_in[2];
    const float* he    = (const float*)d_in[3];
    const float* me    = (const float*)d_in[4];
    const float* ik    = (const float*)d_in[5];
    const float* hk    = (const float*)d_in[6];
    const float* mk    = (const float*)d_in[7];
    const float* AT    = (const float*)d_in[8];
    const float* BT    = (const float*)d_in[9];
    const float* w_c   = (const float*)d_in[10];
    const float* w_h   = (const float*)d_in[11];
    const float* W_lin = (const float*)d_in[12];
    const float* b_lin = (const float*)d_in[13];
    const float* W_ssp = (const float*)d_in[14];
    const float* b_ssp = (const float*)d_in[15];
    float* out = (float*)d_out;

    const int init_smem = (4096 + 128 * 68) * 4;   // 51200 B
    cudaFuncSetAttribute(k_init, cudaFuncAttributeMaxDynamicSharedMemorySize, init_smem);
    cudaFuncSetAttribute(k_proj, cudaFuncAttributeMaxDynamicSharedMemorySize, PJ_SMEM);

    k_init<<<513, 128, init_smem>>>(ssp0, w_c, w_h, W_lin, b_lin, W_ssp, b_ssp,
                                    he, me, ie, ik, hk, mk, AT, BT);
    k_recur<<<128, 544>>>(vel);
    dim3 g(4, 1600);
    k_proj<<<g, 256, PJ_SMEM>>>(out);
}

// round 14
// speedup vs baseline: 1.5568x; 1.1559x over previous
#include <cuda_runtime.h>
#include <cuda_bf16.h>
#include <cuda_fp16.h>

#define T_STEPS 100
#define BATCH   2048
#define NH      128
#define NORD    6
#define NSP     512

typedef unsigned long long ull;
typedef unsigned int u32;

// Scratch (device globals — no allocations allowed).
__device__ __align__(16) __half g_Hf[(size_t)T_STEPS * BATCH * NH];  // fp16 h plane
__device__ __align__(16) __half g_Wph[NSP * NH];                     // Wc fp16 plane
__device__ __align__(16) float g_bc[NSP];

__device__ __forceinline__ void ffma2(ull &d, ull a, ull b) {
    asm("fma.rn.f32x2 %0, %1, %2, %0;" : "+l"(d) : "l"(a), "l"(b));
}
__device__ __forceinline__ float sum2(ull a) {
    float lo, hi;
    asm("mov.b64 {%0,%1}, %2;" : "=f"(lo), "=f"(hi) : "l"(a));
    return lo + hi;
}
__device__ __forceinline__ u32 smem_u32(const void* p) {
    u32 a;
    asm("{ .reg .u64 t; cvta.to.shared.u64 t, %1; cvt.u32.u64 %0, t; }" : "=r"(a) : "l"(p));
    return a;
}
__device__ __forceinline__ __nv_bfloat162 split_bf(float x) {
    __nv_bfloat16 hi = __float2bfloat16(x);
    __nv_bfloat16 lo = __float2bfloat16(x - __bfloat162float(hi));
    __nv_bfloat162 r; r.x = hi; r.y = lo; return r;
}
__device__ __forceinline__ u32 us(__nv_bfloat16 b) {
    return (u32)__bfloat16_as_ushort(b);
}
__device__ __forceinline__ u32 uh(__half h) {
    return (u32)__half_as_ushort(h);
}
__device__ __forceinline__ void ldsm4(u32* r, u32 addr) {
    asm volatile("ldmatrix.sync.aligned.m8n8.x4.shared.b16 {%0,%1,%2,%3}, [%4];"
        : "=r"(r[0]), "=r"(r[1]), "=r"(r[2]), "=r"(r[3]) : "r"(addr));
}
__device__ __forceinline__ void mma16816(float* c, const u32* a, const u32* b) {
    asm volatile(
        "mma.sync.aligned.m16n8k16.row.col.f32.bf16.bf16.f32 "
        "{%0,%1,%2,%3}, {%4,%5,%6,%7}, {%8,%9}, {%0,%1,%2,%3};"
        : "+f"(c[0]), "+f"(c[1]), "+f"(c[2]), "+f"(c[3])
        : "r"(a[0]), "r"(a[1]), "r"(a[2]), "r"(a[3]), "r"(b[0]), "r"(b[1]));
}
__device__ __forceinline__ void mma16816h(float* c, const u32* a, const u32* b) {
    asm volatile(
        "mma.sync.aligned.m16n8k16.row.col.f32.f16.f16.f32 "
        "{%0,%1,%2,%3}, {%4,%5,%6,%7}, {%8,%9}, {%0,%1,%2,%3};"
        : "+f"(c[0]), "+f"(c[1]), "+f"(c[2]), "+f"(c[3])
        : "r"(a[0]), "r"(a[1]), "r"(a[2]), "r"(a[3]), "r"(b[0]), "r"(b[1]));
}
__device__ __forceinline__ void cp16(u32 s, const void* g) {
    asm volatile("cp.async.cg.shared.global [%0], [%1], 16;" :: "r"(s), "l"(g));
}

// W3 element (fused step weight), computed on the fly.
__device__ __forceinline__ float w3val(
    int j, int k, float mkbt,
    const float* __restrict__ he, const float* __restrict__ me,
    const float* __restrict__ ie, const float* __restrict__ ik,
    const float* __restrict__ hk, const float* __restrict__ mk,
    const float* __restrict__ AT, const float* __restrict__ BT) {
    if (j < 128) {
        if (k < 128) return hk[j * 128 + k] + mkbt * he[k];
        if (k < 134) {
            const int p = k - 128;
            float v = mkbt * me[p];
            #pragma unroll
            for (int o = 0; o < 6; o++)
                v += mk[j * 6 + o] * ((o == p ? 1.f : 0.f) + AT[o * 6 + p]);
            return v;
        }
        if (k < 136) return ik[j * 2 + (k - 134)] + mkbt * ie[k - 134];
        return 0.f;
    }
    if (j < 134) {
        const int o = j - 128;
        const float bt = BT[o];
        if (k < 128) return bt * he[k];
        if (k < 134) {
            const int p = k - 128;
            return (o == p ? 1.f : 0.f) + AT[o * 6 + p] + bt * me[p];
        }
        if (k < 136) return bt * ie[k - 134];
    }
    return 0.f;
}

// ---------------------------------------------------------------------------
// Kernel 1: recurrence + embedded init. grid 160 x 544 threads.
//   bids [0,128):   recur CTA (16 batch rows): self-computes h0/m0 (staged
//                   GEMM in dynamic smem) and W3 B-fragments, then 100 steps.
//   bids [128,160): combine CTA: 16 rows of Wc (fp16) + bc (hidden under recur)
// Dynamic smem: s_w 136x64 fp32 | s_s 16 rows stride 68 -> 39168 B.
// Static 32256 B + dynamic 39168 B = 71424 B -> needs opt-in attribute!
// ---------------------------------------------------------------------------
__global__ void __launch_bounds__(544) k_recur(
    const float* __restrict__ vel,   const float* __restrict__ ssp,
    const float* __restrict__ w_c,   const float* __restrict__ w_h,
    const float* __restrict__ W_lin, const float* __restrict__ b_lin,
    const float* __restrict__ W_ssp, const float* __restrict__ b_ssp,
    const float* __restrict__ he,    const float* __restrict__ me,
    const float* __restrict__ ie,    const float* __restrict__ ik,
    const float* __restrict__ hk,    const float* __restrict__ mk,
    const float* __restrict__ AT,    const float* __restrict__ BT) {
    extern __shared__ float dsm[];
    const int tid = threadIdx.x;
    const int bid = blockIdx.x;

    if (bid >= 128) {
        // ================= combine CTA =================
        const int i0 = (bid - 128) * 16;
        for (int i = tid; i < 2048; i += 544)
            ((float4*)dsm)[i] = ((const float4*)(W_ssp + (size_t)i0 * 512))[i];
        __syncthreads();
        if (tid < 512) {
            const int col = tid & 127;
            const int rb = tid >> 7;                  // rows rb, rb+4, rb+8, rb+12
            float a[4][4];
            #pragma unroll
            for (int rr = 0; rr < 4; rr++)
                #pragma unroll
                for (int u = 0; u < 4; u++) a[rr][u] = 0.f;
            for (int j = 0; j < 512; j += 4) {
                float wl[4];
                #pragma unroll
                for (int u = 0; u < 4; u++) wl[u] = W_lin[(j + u) * 128 + col];
                #pragma unroll
                for (int rr = 0; rr < 4; rr++) {
                    const float4 x4 = *(const float4*)(dsm + (rb + 4 * rr) * 512 + j);
                    a[rr][0] += x4.x * wl[0]; a[rr][1] += x4.y * wl[1];
                    a[rr][2] += x4.z * wl[2]; a[rr][3] += x4.w * wl[3];
                }
            }
            #pragma unroll
            for (int rr = 0; rr < 4; rr++) {
                const float v = (a[rr][0] + a[rr][1]) + (a[rr][2] + a[rr][3]);
                g_Wph[(size_t)(i0 + rb + 4 * rr) * NH + col] = __float2half_rn(v);
            }
        } else if (tid < 528) {
            const int row = tid - 512;
            float a0 = 0.f, a1 = 0.f, a2 = 0.f, a3 = 0.f;
            for (int j = 0; j < 512; j += 4) {
                const float4 b4 = *(const float4*)(b_lin + j);
                const float4 x4 = *(const float4*)(dsm + row * 512 + j);
                a0 += x4.x * b4.x; a1 += x4.y * b4.y;
                a2 += x4.z * b4.z; a3 += x4.w * b4.w;
            }
            g_bc[i0 + row] = b_ssp[i0 + row] + (a0 + a1) + (a2 + a3);
        }
        return;
    }

    // ================= recur CTA =================
    __shared__ __align__(16) unsigned char s_xb[19456]; // 2 bufs x 2 planes x 16 x 304B
    __shared__ float s_v[3200];                         // [100][16][2]
    const int b0 = bid * 16;
    const u32 xb = smem_u32(s_xb);
    const int lane = tid & 31, w = tid >> 5;

    for (int i = tid; i < 19456 / 4; i += 544) ((u32*)s_xb)[i] = 0;
    for (int i = tid; i < 3200; i += 544)
        s_v[i] = vel[(size_t)(i >> 5) * (BATCH * 2) + b0 * 2 + (i & 31)];

    // ---- B fragments computed directly from inputs (gmem only) ----
    const int colB = 8 * w + (lane >> 2);
    float mkbt = 0.f;
    if (colB < 128) {
        #pragma unroll
        for (int o = 0; o < 6; o++) mkbt += mk[colB * 6 + o] * BT[o];
    }
    u32 bh[9][2], bl[9][2];
    #pragma unroll
    for (int ks = 0; ks < 9; ks++) {
        #pragma unroll
        for (int rr = 0; rr < 2; rr++) {
            const int k0 = ks * 16 + 2 * (lane & 3) + rr * 8;
            const float v0 = w3val(colB, k0,     mkbt, he, me, ie, ik, hk, mk, AT, BT);
            const float v1 = w3val(colB, k0 + 1, mkbt, he, me, ie, ik, hk, mk, AT, BT);
            const __nv_bfloat162 p0 = split_bf(v0), p1 = split_bf(v1);
            bh[ks][rr] = us(p0.x) | (us(p1.x) << 16);
            bl[ks][rr] = us(p0.y) | (us(p1.y) << 16);
        }
    }

    // ---- setup GEMM: x0 = [h0 | m0] = ssp(16x512) @ [w_h; w_c]^T ----
    // dsm: s_w 136 rows x 64 (offset 0), s_s 16 rows x stride 68 (offset 8704)
    const int r_set = tid & 15;
    const int j_set = tid >> 4;          // 0..33; outputs j_set + 34u
    ull sac[4];
    #pragma unroll
    for (int u = 0; u < 4; u++) sac[u] = 0ull;

    #pragma unroll 1
    for (int kt = 0; kt < 8; kt++) {
        __syncthreads();     // scratch reuse (and first-iter: covers zero/s_v)
        for (int i = tid; i < 2176; i += 544) {
            const int row = i >> 4, c4 = i & 15;
            float4 v;
            if (row < 128)       v = *(const float4*)(w_h + row * 512 + kt * 64 + c4 * 4);
            else if (row < 134)  v = *(const float4*)(w_c + (row - 128) * 512 + kt * 64 + c4 * 4);
            else                 v = make_float4(0.f, 0.f, 0.f, 0.f);
            *(float4*)(dsm + row * 64 + c4 * 4) = v;
        }
        for (int i = tid; i < 256; i += 544) {
            const int row = i >> 4, c4 = i & 15;
            *(float4*)(dsm + 8704 + row * 68 + c4 * 4) =
                *(const float4*)(ssp + (size_t)(b0 + row) * 512 + kt * 64 + c4 * 4);
        }
        __syncthreads();
        #pragma unroll 4
        for (int k4 = 0; k4 < 16; k4++) {
            const ulonglong2 xp = *(const ulonglong2*)(dsm + 8704 + r_set * 68 + k4 * 4);
            #pragma unroll
            for (int u = 0; u < 4; u++) {
                const ulonglong2 wp = *(const ulonglong2*)(dsm + (j_set + 34 * u) * 64 + k4 * 4);
                ffma2(sac[u], xp.x, wp.x);
                ffma2(sac[u], xp.y, wp.y);
            }
        }
    }
    // write x(0) planes (hi at 0, lo at 4864)
    #pragma unroll
    for (int u = 0; u < 4; u++) {
        const int j = j_set + 34 * u;
        if (j < 134) {
            const __nv_bfloat162 p = split_bf(sum2(sac[u]));
            *(__nv_bfloat16*)(s_xb + r_set * 304 + j * 2) = p.x;
            *(__nv_bfloat16*)(s_xb + 4864 + r_set * 304 + j * 2) = p.y;
        }
    }
    if (tid < 32) {
        const int r = tid >> 1, c = tid & 1;
        const __nv_bfloat162 p = split_bf(s_v[r * 2 + c]);
        *(__nv_bfloat16*)(s_xb + r * 304 + (134 + c) * 2) = p.x;
        *(__nv_bfloat16*)(s_xb + 4864 + r * 304 + (134 + c) * 2) = p.y;
    }
    __syncthreads();

    // ---- main loop (unchanged from R11/R12) ----
    const int r0 = lane >> 2;
    const int c0 = 8 * w + 2 * (lane & 3);
    const u32 a_off = (u32)((lane & 15) * 304 + (lane >> 4) * 16);

    #pragma unroll 1
    for (int t = 0; t < T_STEPS; t++) {
        const u32 xro = (u32)(t & 1) * 9728;
        const u32 xwo = xro ^ 9728;
        float a_hh[4] = {0.f, 0.f, 0.f, 0.f};
        float a_lh[4] = {0.f, 0.f, 0.f, 0.f};
        float a_hl[4] = {0.f, 0.f, 0.f, 0.f};

        #pragma unroll
        for (int ks = 0; ks < 9; ks++) {
            u32 ah[4], al[4];
            ldsm4(ah, xb + xro + a_off + ks * 32);
            ldsm4(al, xb + xro + 4864 + a_off + ks * 32);
            mma16816(a_hh, ah, bh[ks]);
            mma16816(a_lh, al, bh[ks]);
            mma16816(a_hl, ah, bl[ks]);
        }
        float acc[4];
        #pragma unroll
        for (int i = 0; i < 4; i++) acc[i] = a_hh[i] + (a_lh[i] + a_hl[i]);

        if (c0 < 128) {
            float hv[4];
            #pragma unroll
            for (int i = 0; i < 4; i++) {
                const float e = __expf(2.f * acc[i]);
                hv[i] = 1.f - __fdividef(2.f, e + 1.f);
            }
            const __nv_bfloat162 s00 = split_bf(hv[0]), s01 = split_bf(hv[1]);
            const __nv_bfloat162 s10 = split_bf(hv[2]), s11 = split_bf(hv[3]);
            *(u32*)(s_xb + xwo + r0 * 304 + c0 * 2)              = us(s00.x) | (us(s01.x) << 16);
            *(u32*)(s_xb + xwo + 4864 + r0 * 304 + c0 * 2)       = us(s00.y) | (us(s01.y) << 16);
            *(u32*)(s_xb + xwo + (r0 + 8) * 304 + c0 * 2)        = us(s10.x) | (us(s11.x) << 16);
            *(u32*)(s_xb + xwo + 4864 + (r0 + 8) * 304 + c0 * 2) = us(s10.y) | (us(s11.y) << 16);
            const size_t go = ((size_t)t * BATCH + b0 + r0) * NH + c0;
            *(u32*)(g_Hf + go) =
                uh(__float2half_rn(hv[0])) | (uh(__float2half_rn(hv[1])) << 16);
            *(u32*)(g_Hf + go + 8 * NH) =
                uh(__float2half_rn(hv[2])) | (uh(__float2half_rn(hv[3])) << 16);
        } else if (c0 < 134) {
            const __nv_bfloat162 s00 = split_bf(acc[0]), s01 = split_bf(acc[1]);
            const __nv_bfloat162 s10 = split_bf(acc[2]), s11 = split_bf(acc[3]);
            *(u32*)(s_xb + xwo + r0 * 304 + c0 * 2)        = us(s00.x) | (us(s01.x) << 16);
            *(u32*)(s_xb + xwo + 4864 + r0 * 304 + c0 * 2) = us(s00.y) | (us(s01.y) << 16);
            *(u32*)(s_xb + xwo + (r0 + 8) * 304 + c0 * 2)        = us(s10.x) | (us(s11.x) << 16);
            *(u32*)(s_xb + xwo + 4864 + (r0 + 8) * 304 + c0 * 2) = us(s10.y) | (us(s11.y) << 16);
        } else if (t < T_STEPS - 1) {
            const __nv_bfloat162 a0 = split_bf(s_v[(t + 1) * 32 + r0 * 2]);
            const __nv_bfloat162 a1 = split_bf(s_v[(t + 1) * 32 + r0 * 2 + 1]);
            const __nv_bfloat162 b0s = split_bf(s_v[(t + 1) * 32 + (r0 + 8) * 2]);
            const __nv_bfloat162 b1s = split_bf(s_v[(t + 1) * 32 + (r0 + 8) * 2 + 1]);
            *(u32*)(s_xb + xwo + r0 * 304 + 268)        = us(a0.x) | (us(a1.x) << 16);
            *(u32*)(s_xb + xwo + 4864 + r0 * 304 + 268) = us(a0.y) | (us(a1.y) << 16);
            *(u32*)(s_xb + xwo + (r0 + 8) * 304 + 268)        = us(b0s.x) | (us(b1s.x) << 16);
            *(u32*)(s_xb + xwo + 4864 + (r0 + 8) * 304 + 268) = us(b0s.y) | (us(b1s.y) << 16);
        }
        __syncthreads();
    }
}

// ---------------------------------------------------------------------------
// Kernel 2: projection — fp16 single-pass HMMA (unchanged from R12).
// ---------------------------------------------------------------------------
#define PJ_A  0
#define PJ_BH 32768
#define PJ_SMEM 65536

__global__ void __launch_bounds__(256, 2) k_proj(float* __restrict__ out) {
    extern __shared__ char smc[];
    const u32 sb = smem_u32(smc);
    const int tid = threadIdx.x;
    const int w = tid >> 5, lane = tid & 31;
    const int col0 = blockIdx.x * 128;
    const int row0 = blockIdx.y * 128;

    const int wm = w & 1, wn = w >> 1;
    const int mbase = wm * 64, nbase = wn * 32;
    const int arow_l = lane & 15, asel = lane >> 4;
    const int brow_l = ((lane >> 4) << 3) + (lane & 7), bsel = (lane >> 3) & 1;

    for (int idx = tid; idx < 2048; idx += 256) {
        const int row = idx >> 4, c16 = idx & 15;
        const u32 so = (u32)row * 256 + ((u32)((c16 ^ (row & 7)) << 4));
        cp16(sb + PJ_A + so, g_Hf + (size_t)(row0 + row) * NH + c16 * 8);
        cp16(sb + PJ_BH + so, g_Wph + (size_t)(col0 + row) * NH + c16 * 8);
    }
    asm volatile("cp.async.commit_group;");
    asm volatile("cp.async.wait_group 0;");
    __syncthreads();

    float acc[4][4][4];
    #pragma unroll
    for (int mt = 0; mt < 4; mt++)
        #pragma unroll
        for (int nt = 0; nt < 4; nt++)
            #pragma unroll
            for (int i = 0; i < 4; i++) acc[mt][nt][i] = 0.f;

    #pragma unroll
    for (int kk = 0; kk < 8; kk++) {
        u32 a[4][4];
        #pragma unroll
        for (int mt = 0; mt < 4; mt++) {
            const int row = mbase + mt * 16 + arow_l;
            const u32 off = (u32)row * 256 + ((u32)(((2 * kk + asel) ^ (row & 7)) << 4));
            ldsm4(a[mt], sb + PJ_A + off);
        }
        u32 bhi[2][4];
        #pragma unroll
        for (int np = 0; np < 2; np++) {
            const int row = nbase + np * 16 + brow_l;
            const u32 off = (u32)row * 256 + ((u32)(((2 * kk + bsel) ^ (row & 7)) << 4));
            ldsm4(bhi[np], sb + PJ_BH + off);
        }
        #pragma unroll
        for (int mt = 0; mt < 4; mt++) {
            #pragma unroll
            for (int nt = 0; nt < 4; nt++) {
                mma16816h(acc[mt][nt], a[mt], &bhi[nt >> 1][(nt & 1) * 2]);
            }
        }
    }

    const int tq = lane >> 2, tr = lane & 3;
    #pragma unroll
    for (int nt = 0; nt < 4; nt++) {
        const int ncol = col0 + nbase + nt * 8 + tr * 2;
        const float2 bias = *(const float2*)(g_bc + ncol);
        #pragma unroll
        for (int mt = 0; mt < 4; mt++) {
            const int mrow = row0 + mbase + mt * 16 + tq;
            float2 v0, v1;
            v0.x = acc[mt][nt][0] + bias.x; v0.y = acc[mt][nt][1] + bias.y;
            v1.x = acc[mt][nt][2] + bias.x; v1.y = acc[mt][nt][3] + bias.y;
            *(float2*)(out + (size_t)mrow * NSP + ncol) = v0;
            *(float2*)(out + (size_t)(mrow + 8) * NSP + ncol) = v1;
        }
    }
}

// ---------------------------------------------------------------------------
extern "C" void kernel_launch(void* const* d_in, const int* in_sizes, int n_in,
                              void* d_out, int out_size) {
    const float* vel   = (const float*)d_in[0];
    const float* ssp0  = (const float*)d_in[1];
    const float* ie    = (const float*)d_in[2];
    const float* he    = (const float*)d_in[3];
    const float* me    = (const float*)d_in[4];
    const float* ik    = (const float*)d_in[5];
    const float* hk    = (const float*)d_in[6];
    const float* mk    = (const float*)d_in[7];
    const float* AT    = (const float*)d_in[8];
    const float* BT    = (const float*)d_in[9];
    const float* w_c   = (const float*)d_in[10];
    const float* w_h   = (const float*)d_in[11];
    const float* W_lin = (const float*)d_in[12];
    const float* b_lin = (const float*)d_in[13];
    const float* W_ssp = (const float*)d_in[14];
    const float* b_ssp = (const float*)d_in[15];
    float* out = (float*)d_out;

    const int recur_dsm = (136 * 64 + 16 * 68) * 4;   // 39168 B (static 32256 + this > 48K)
    cudaFuncSetAttribute(k_recur, cudaFuncAttributeMaxDynamicSharedMemorySize, recur_dsm);
    cudaFuncSetAttribute(k_proj,  cudaFuncAttributeMaxDynamicSharedMemorySize, PJ_SMEM);

    k_recur<<<160, 544, recur_dsm>>>(vel, ssp0, w_c, w_h, W_lin, b_lin, W_ssp, b_ssp,
                                     he, me, ie, ik, hk, mk, AT, BT);
    dim3 g(4, 1600);
    k_proj<<<g, 256, PJ_SMEM>>>(out);
}